// round 2
// baseline (speedup 1.0000x reference)
#include <cuda_runtime.h>
#include <cuda_bf16.h>
#include <cstdint>

#define Bc   32
#define Tc   400
#define Jc   30
#define Hc   150
#define H2c  300
#define H3c  450
#define TP1c 401
#define KP4  38           // ceil(150/4); k padded to 152 with zeros
#define PACK_ELEMS (KP4*H3c*4)   // 68400 floats per packed weight

// ---------------- device scratch ----------------
__device__ float g_gictx[Bc*Tc*H3c];
__device__ float g_giq  [Bc*Jc*H3c];
__device__ float g_Hp   [Bc*Tc*Hc];
__device__ float g_Hq   [Bc*Jc*Hc];
__device__ float g_whq  [Bc*Jc*Hc];
__device__ float g_preWp[Bc*Tc*Hc];
__device__ float g_gixf [Bc*Tc*H3c];
__device__ float g_gixb [Bc*Tc*H3c];
__device__ float g_qpf  [Bc*Jc*H3c];
__device__ float g_qpb  [Bc*Jc*H3c];
__device__ float g_Hr   [Bc*TP1c*H2c];
__device__ float g_enc  [Bc*TP1c*H2c];
__device__ float g_packs[4*PACK_ELEMS];

// ---------------- fast activations ----------------
__device__ __forceinline__ float fast_ex2(float x){ float y; asm("ex2.approx.f32 %0, %1;" : "=f"(y) : "f"(x)); return y; }
__device__ __forceinline__ float sigm(float x){ return __fdividef(1.f, 1.f + fast_ex2(-1.442695041f*x)); }
__device__ __forceinline__ float tanh_f(float x){
  x = fminf(fmaxf(x, -15.f), 15.f);
  float t = fast_ex2(2.885390082f*x);
  return __fdividef(t - 1.f, t + 1.f);
}

// ---------------- weight transpose-pack: out[(k4*450+n)*4+kk] = W[n*ldw+koff+k4*4+kk] ----------------
__global__ void pack_kernel(const float* __restrict__ W, float* __restrict__ out, int ldw, int koff)
{
  int i = blockIdx.x*blockDim.x + threadIdx.x;
  if (i >= PACK_ELEMS) return;
  int kk = i & 3;
  int n  = (i >> 2) % H3c;
  int k4 = (i >> 2) / H3c;
  int k  = k4*4 + kk;
  out[i] = (k < Hc) ? W[n*ldw + koff + k] : 0.f;
}

// ---------------- generic tiled GEMM ----------------
// C[m,n] = sum_k Arow(m)[k] * W(n,k) + bias[n]
// TRANSW:  W(n,k) = W[n*ldw + k]    (X @ W^T layout)
// !TRANSW: W(n,k) = W[k*ldw + n]    (X @ W layout)
// GATHER:  Arow(m) = A + idx[m]*lda
template<bool TRANSW, bool GATHER>
__global__ void __launch_bounds__(256) gemm_kernel(
    const float* __restrict__ A, const int* __restrict__ idx,
    const float* __restrict__ W, const float* __restrict__ bias,
    float* __restrict__ C, int M, int N, int K, int lda, int ldw)
{
  __shared__ float As[16][68];
  __shared__ float Bs[16][68];
  int m0 = blockIdx.y*64, n0 = blockIdx.x*64;
  int tid = threadIdx.x;
  int tx = tid & 15, ty = tid >> 4;
  float acc[4][4] = {};

  for (int k0 = 0; k0 < K; k0 += 16) {
    #pragma unroll
    for (int it = 0; it < 4; it++) {
      int li = tid + it*256;
      int m = li >> 4, k = li & 15;
      float v = 0.f;
      int gm = m0 + m, gk = k0 + k;
      if (gm < M && gk < K) {
        int row = GATHER ? idx[gm] : gm;
        v = A[(size_t)row*lda + gk];
      }
      As[k][m] = v;
    }
    #pragma unroll
    for (int it = 0; it < 4; it++) {
      int li = tid + it*256;
      float v = 0.f;
      if (TRANSW) {
        int n = li >> 4, k = li & 15;
        int gn = n0+n, gk = k0+k;
        if (gn < N && gk < K) v = W[(size_t)gn*ldw + gk];
        Bs[k][n] = v;
      } else {
        int k = li >> 6, n = li & 63;
        int gn = n0+n, gk = k0+k;
        if (gn < N && gk < K) v = W[(size_t)gk*ldw + gn];
        Bs[k][n] = v;
      }
    }
    __syncthreads();
    #pragma unroll
    for (int k = 0; k < 16; k++) {
      float4 bv = *reinterpret_cast<const float4*>(&Bs[k][tx*4]);
      float a0 = As[k][ty*4+0], a1 = As[k][ty*4+1], a2 = As[k][ty*4+2], a3 = As[k][ty*4+3];
      acc[0][0]=fmaf(a0,bv.x,acc[0][0]); acc[0][1]=fmaf(a0,bv.y,acc[0][1]); acc[0][2]=fmaf(a0,bv.z,acc[0][2]); acc[0][3]=fmaf(a0,bv.w,acc[0][3]);
      acc[1][0]=fmaf(a1,bv.x,acc[1][0]); acc[1][1]=fmaf(a1,bv.y,acc[1][1]); acc[1][2]=fmaf(a1,bv.z,acc[1][2]); acc[1][3]=fmaf(a1,bv.w,acc[1][3]);
      acc[2][0]=fmaf(a2,bv.x,acc[2][0]); acc[2][1]=fmaf(a2,bv.y,acc[2][1]); acc[2][2]=fmaf(a2,bv.z,acc[2][2]); acc[2][3]=fmaf(a2,bv.w,acc[2][3]);
      acc[3][0]=fmaf(a3,bv.x,acc[3][0]); acc[3][1]=fmaf(a3,bv.y,acc[3][1]); acc[3][2]=fmaf(a3,bv.z,acc[3][2]); acc[3][3]=fmaf(a3,bv.w,acc[3][3]);
    }
    __syncthreads();
  }
  #pragma unroll
  for (int i = 0; i < 4; i++) {
    int gm = m0 + ty*4 + i;
    if (gm >= M) continue;
    #pragma unroll
    for (int j = 0; j < 4; j++) {
      int gn = n0 + tx*4 + j;
      if (gn < N) {
        float v = acc[i][j];
        if (bias) v += bias[gn];
        C[(size_t)gm*N + gn] = v;
      }
    }
  }
}

// ---------------- batch-parallel GRU scans (blocks 0..31 ctx, 32..63 query) ----------------
__global__ void __launch_bounds__(512,1) gru_scan_kernel(
    const float* __restrict__ gictx, const float* __restrict__ giq,
    const float4* __restrict__ PctxWhh, const float4* __restrict__ PqWhh,
    const float* __restrict__ ctx_bhh, const float* __restrict__ q_bhh,
    float* __restrict__ Hp, float* __restrict__ Hq)
{
  __shared__ float sh[152];
  __shared__ float sgh[452];
  int tid = threadIdx.x;
  int isq = blockIdx.x >> 5;
  int b   = blockIdx.x & 31;
  const float*  gi   = isq ? (giq + (size_t)b*Jc*H3c) : (gictx + (size_t)b*Tc*H3c);
  const float4* Wp4  = isq ? PqWhh : PctxWhh;
  const float*  bhh  = isq ? q_bhh : ctx_bhh;
  float*        outp = isq ? (Hq + (size_t)b*Jc*Hc) : (Hp + (size_t)b*Tc*Hc);
  int Tlen = isq ? Jc : Tc;

  float my_b = (tid < H3c) ? bhh[tid] : 0.f;
  if (tid < 152) sh[tid] = 0.f;
  __syncthreads();

  for (int t = 0; t < Tlen; t++) {
    if (tid < H3c) {
      float acc = my_b;
      const float4* wr = Wp4 + tid;
      #pragma unroll
      for (int k4 = 0; k4 < KP4; k4++) {
        float4 h4 = *reinterpret_cast<const float4*>(sh + k4*4);
        float4 w4 = wr[(size_t)k4*H3c];
        acc = fmaf(h4.x,w4.x,fmaf(h4.y,w4.y,fmaf(h4.z,w4.z,fmaf(h4.w,w4.w,acc))));
      }
      sgh[tid] = acc;
    }
    __syncthreads();
    if (tid < Hc) {
      const float* gr = gi + (size_t)t*H3c;
      float r  = sigm(gr[tid]        + sgh[tid]);
      float z  = sigm(gr[Hc + tid]   + sgh[Hc + tid]);
      float nn = tanh_f(gr[2*Hc+tid] + r*sgh[2*Hc + tid]);
      float hn = nn + z*(sh[tid] - nn);
      sh[tid] = hn;
      outp[(size_t)t*Hc + tid] = hn;
    }
    __syncthreads();
  }
}

// ---------------- match scans (blocks 0..31 fwd, 32..63 rev) ----------------
// dynamic smem: sWrT[150*164] | sWhq[30*150] | sQP[30*450]
#define SWRT_STRIDE 164
#define DSMEM_FLOATS (Hc*SWRT_STRIDE + Jc*Hc + Jc*H3c)  // 24600+4500+13500 = 42600

__global__ void __launch_bounds__(512,1) match_kernel(
    const float* __restrict__ whq,  const float* __restrict__ preWp,
    const float* __restrict__ gixf, const float* __restrict__ gixb,
    const float* __restrict__ qpf,  const float* __restrict__ qpb,
    const float* __restrict__ Wr,   const float* __restrict__ wvec,
    const float4* __restrict__ WhPf, const float4* __restrict__ WhPb,
    const float* __restrict__ m_bhh, const float* __restrict__ mr_bhh,
    float* __restrict__ Hr)
{
  extern __shared__ float dsm[];
  float* sWrT = dsm;                          // [150][164] transposed Wr, padded rows
  float* sWhq = dsm + Hc*SWRT_STRIDE;         // [30][150]
  float* sQP  = sWhq + Jc*Hc;                 // [30][450]
  __shared__ float sw [152];
  __shared__ float sh [152];
  __shared__ float se [152];
  __shared__ float sgi[452];
  __shared__ float sgh[452];
  __shared__ float sS [32];
  __shared__ float sA [32];

  int tid = threadIdx.x;
  int dir = blockIdx.x >> 5;
  int b   = blockIdx.x & 31;

  const float*  gix = (dir ? gixb : gixf) + (size_t)b*Tc*H3c;
  const float*  qp  = (dir ? qpb  : qpf)  + (size_t)b*Jc*H3c;
  const float4* WhP = dir ? WhPb : WhPf;
  const float*  bhh = dir ? mr_bhh : m_bhh;
  const float*  preW = preWp + (size_t)b*Tc*Hc;

  for (int i = tid; i < Hc*Hc; i += 512) { int j = i/Hc, k = i%Hc; sWrT[k*SWRT_STRIDE + j] = Wr[i]; }
  for (int i = tid; i < Jc*Hc; i += 512) sWhq[i] = whq[(size_t)b*Jc*Hc + i];
  for (int i = tid; i < Jc*H3c; i += 512) sQP[i] = qp[i];
  if (tid < 152) { sw[tid] = (tid < Hc) ? wvec[tid] : 0.f; sh[tid] = 0.f; }
  if (tid < Hc)  { sWrT[tid*SWRT_STRIDE + 150] = 0.f; sWrT[tid*SWRT_STRIDE + 151] = 0.f;
                   Hr[((size_t)b*TP1c)*H2c + dir*Hc + tid] = 0.f; }
  float my_bhh = (tid < H3c) ? bhh[tid] : 0.f;
  __syncthreads();

  for (int step = 0; step < Tc; step++) {
    int t = dir ? (Tc-1-step) : step;

    // phase1: e = preWp[t] (incl gate_bias) + h @ Wr
    if (tid < Hc) {
      float acc = preW[(size_t)t*Hc + tid];
      const float4* row = reinterpret_cast<const float4*>(sWrT + tid*SWRT_STRIDE);
      #pragma unroll
      for (int k4 = 0; k4 < KP4; k4++) {
        float4 h4 = *reinterpret_cast<const float4*>(sh + k4*4);
        float4 w4 = row[k4];
        acc = fmaf(h4.x,w4.x,fmaf(h4.y,w4.y,fmaf(h4.z,w4.z,fmaf(h4.w,w4.w,acc))));
      }
      se[tid] = acc;
    }
    __syncthreads();

    // phase2: s_j = sum_k tanh(whq[j,k] + e[k]) * w[k]   (attn_bias softmax-invariant)
    {
      int wid = tid >> 5, lane = tid & 31;
      if (wid < 15) {
        #pragma unroll
        for (int jj = 0; jj < 2; jj++) {
          int j = wid*2 + jj;
          float p = 0.f;
          for (int k = lane; k < Hc; k += 32)
            p = fmaf(tanh_f(sWhq[j*Hc + k] + se[k]), sw[k], p);
          #pragma unroll
          for (int o = 16; o; o >>= 1) p += __shfl_xor_sync(0xffffffffu, p, o);
          if (lane == 0) sS[j] = p;
        }
      }
    }
    __syncthreads();

    // phase3: softmax over J=30 (warp 0)
    if (tid < 32) {
      float v = (tid < Jc) ? sS[tid] : -1e30f;
      float m = v;
      #pragma unroll
      for (int o = 16; o; o >>= 1) m = fmaxf(m, __shfl_xor_sync(0xffffffffu, m, o));
      float e = (tid < Jc) ? fast_ex2(1.442695041f*(v - m)) : 0.f;
      float su = e;
      #pragma unroll
      for (int o = 16; o; o >>= 1) su += __shfl_xor_sync(0xffffffffu, su, o);
      sA[tid] = e * __fdividef(1.f, su);
    }
    __syncthreads();

    // phase4: gates. gi = gix[t] + sum_j a_j * qproj[j];  gh = bhh + h @ Whh^T
    if (tid < H3c) {
      float gh = my_bhh;
      const float4* wh = WhP + tid;
      #pragma unroll
      for (int k4 = 0; k4 < KP4; k4++) {
        float4 h4 = *reinterpret_cast<const float4*>(sh + k4*4);
        float4 w4 = wh[(size_t)k4*H3c];
        gh = fmaf(h4.x,w4.x,fmaf(h4.y,w4.y,fmaf(h4.z,w4.z,fmaf(h4.w,w4.w,gh))));
      }
      float gi = gix[(size_t)t*H3c + tid];
      #pragma unroll
      for (int j = 0; j < Jc; j++) gi = fmaf(sA[j], sQP[j*H3c + tid], gi);
      sgi[tid] = gi; sgh[tid] = gh;
    }
    __syncthreads();

    // phase5: GRU update + write Hr (storage index = scan step)
    if (tid < Hc) {
      float r  = sigm(sgi[tid] + sgh[tid]);
      float z  = sigm(sgi[Hc+tid] + sgh[Hc+tid]);
      float nn = tanh_f(sgi[2*Hc+tid] + r*sgh[2*Hc+tid]);
      float hn = nn + z*(sh[tid] - nn);
      sh[tid] = hn;
      Hr[((size_t)b*TP1c + 1 + step)*H2c + dir*Hc + tid] = hn;
    }
    __syncthreads();
  }
}

// ---------------- pointer decoder (32 blocks, 2 steps) ----------------
__global__ void __launch_bounds__(512,1) ptr_kernel(
    const float* __restrict__ Hr, const float* __restrict__ enc,
    const float* __restrict__ ptr_W2, const float* __restrict__ ptr_v,
    const float* __restrict__ d_Wih, const float* __restrict__ d_Whh,
    const float* __restrict__ d_bih, const float* __restrict__ d_bhh,
    float* __restrict__ out)
{
  __shared__ float sh[H2c], shw[H2c], sc[H2c], sa[TP1c + 3], sgi[900], sgh[900];
  __shared__ float red[2];
  int b = blockIdx.x, tid = threadIdx.x;
  int wid = tid >> 5, lane = tid & 31;
  const float* encb = enc + (size_t)b*TP1c*H2c;
  const float* Hrb  = Hr  + (size_t)b*TP1c*H2c;
  if (tid < H2c) sh[tid] = 0.f;
  __syncthreads();

  for (int step = 0; step < 2; step++) {
    // hw2 = h @ ptr_W2
    if (tid < H2c) {
      float a = 0.f;
      for (int j = 0; j < H2c; j++) a = fmaf(sh[j], ptr_W2[(size_t)j*H2c + tid], a);
      shw[tid] = a;
    }
    __syncthreads();
    // scores over T+1 positions
    for (int t = wid; t < TP1c; t += 16) {
      float p = 0.f;
      const float* er = encb + (size_t)t*H2c;
      for (int k = lane; k < H2c; k += 32) p = fmaf(tanh_f(er[k] + shw[k]), ptr_v[k], p);
      #pragma unroll
      for (int o = 16; o; o >>= 1) p += __shfl_xor_sync(0xffffffffu, p, o);
      if (lane == 0) sa[t] = p;
    }
    __syncthreads();
    // softmax over 401
    if (tid < 32) {
      float m = -1e30f;
      for (int t = lane; t < TP1c; t += 32) m = fmaxf(m, sa[t]);
      #pragma unroll
      for (int o = 16; o; o >>= 1) m = fmaxf(m, __shfl_xor_sync(0xffffffffu, m, o));
      if (lane == 0) red[0] = m;
    }
    __syncthreads();
    float mm = red[0];
    for (int t = tid; t < TP1c; t += 512) sa[t] = fast_ex2(1.442695041f*(sa[t] - mm));
    __syncthreads();
    if (tid < 32) {
      float s = 0.f;
      for (int t = lane; t < TP1c; t += 32) s += sa[t];
      #pragma unroll
      for (int o = 16; o; o >>= 1) s += __shfl_xor_sync(0xffffffffu, s, o);
      if (lane == 0) red[1] = __fdividef(1.f, s);
    }
    __syncthreads();
    float inv = red[1];
    for (int t = tid; t < TP1c; t += 512) {
      float a = sa[t] * inv;
      sa[t] = a;
      out[((size_t)b*2 + step)*TP1c + t] = a;
    }
    __syncthreads();
    // c = a @ Hr
    if (tid < H2c) {
      float a = 0.f;
      for (int t = 0; t < TP1c; t++) a = fmaf(sa[t], Hrb[(size_t)t*H2c + tid], a);
      sc[tid] = a;
    }
    __syncthreads();
    // decoder GRU (hidden 300, gates 900)
    for (int n = tid; n < 900; n += 512) {
      float gi = d_bih[n], gh = d_bhh[n];
      const float* wi = d_Wih + (size_t)n*H2c;
      const float* wh = d_Whh + (size_t)n*H2c;
      for (int k = 0; k < H2c; k++) { gi = fmaf(sc[k], wi[k], gi); gh = fmaf(sh[k], wh[k], gh); }
      sgi[n] = gi; sgh[n] = gh;
    }
    __syncthreads();
    if (tid < H2c) {
      float r  = sigm(sgi[tid] + sgh[tid]);
      float z  = sigm(sgi[H2c+tid] + sgh[H2c+tid]);
      float nn = tanh_f(sgi[2*H2c+tid] + r*sgh[2*H2c+tid]);
      sh[tid] = nn + z*(sh[tid] - nn);
    }
    __syncthreads();
  }
}

// ---------------- host ----------------
static void* sym(const void* s) { void* p = nullptr; cudaGetSymbolAddress(&p, s); return p; }

extern "C" void kernel_launch(void* const* d_in, const int* in_sizes, int n_in,
                              void* d_out, int out_size)
{
  const int*   context = (const int*)  d_in[0];
  const int*   query   = (const int*)  d_in[1];
  const float* E       = (const float*)d_in[2];
  const float* ctx_Wih = (const float*)d_in[3];
  const float* ctx_Whh = (const float*)d_in[4];
  const float* ctx_bih = (const float*)d_in[5];
  const float* ctx_bhh = (const float*)d_in[6];
  const float* q_Wih   = (const float*)d_in[7];
  const float* q_Whh   = (const float*)d_in[8];
  const float* q_bih   = (const float*)d_in[9];
  const float* q_bhh   = (const float*)d_in[10];
  const float* Wq      = (const float*)d_in[11];
  const float* Wp      = (const float*)d_in[12];
  const float* Wr      = (const float*)d_in[13];
  const float* wv      = (const float*)d_in[14];
  const float* gate_b  = (const float*)d_in[15];
  // d_in[16] = attn_bias (scalar, softmax-invariant -> unused)
  const float* m_Wih   = (const float*)d_in[17];
  const float* m_Whh   = (const float*)d_in[18];
  const float* m_bih   = (const float*)d_in[19];
  const float* m_bhh   = (const float*)d_in[20];
  const float* mr_Wih  = (const float*)d_in[21];
  const float* mr_Whh  = (const float*)d_in[22];
  const float* mr_bih  = (const float*)d_in[23];
  const float* mr_bhh  = (const float*)d_in[24];
  const float* ptr_W1  = (const float*)d_in[25];
  const float* ptr_W2  = (const float*)d_in[26];
  const float* ptr_v   = (const float*)d_in[27];
  const float* d_Wih   = (const float*)d_in[28];
  const float* d_Whh   = (const float*)d_in[29];
  const float* d_bih   = (const float*)d_in[30];
  const float* d_bhh   = (const float*)d_in[31];
  float* out = (float*)d_out;

  float* gictx = (float*)sym(g_gictx);
  float* giq   = (float*)sym(g_giq);
  float* Hp    = (float*)sym(g_Hp);
  float* Hq    = (float*)sym(g_Hq);
  float* whq   = (float*)sym(g_whq);
  float* preWp = (float*)sym(g_preWp);
  float* gixf  = (float*)sym(g_gixf);
  float* gixb  = (float*)sym(g_gixb);
  float* qpf   = (float*)sym(g_qpf);
  float* qpb   = (float*)sym(g_qpb);
  float* Hr    = (float*)sym(g_Hr);
  float* enc   = (float*)sym(g_enc);
  float* packs = (float*)sym(g_packs);
  float* P_ctx = packs + 0*PACK_ELEMS;
  float* P_q   = packs + 1*PACK_ELEMS;
  float* P_m   = packs + 2*PACK_ELEMS;
  float* P_mr  = packs + 3*PACK_ELEMS;

  int pk_grid = (PACK_ELEMS + 255)/256;
  pack_kernel<<<pk_grid,256>>>(ctx_Whh, P_ctx, Hc, 0);
  pack_kernel<<<pk_grid,256>>>(q_Whh,   P_q,   Hc, 0);
  pack_kernel<<<pk_grid,256>>>(m_Whh,   P_m,   Hc, 0);
  pack_kernel<<<pk_grid,256>>>(mr_Whh,  P_mr,  Hc, 0);

  // gi projections of embedded tokens
  gemm_kernel<true,true><<<dim3(8,200),256>>>(E, context, ctx_Wih, ctx_bih, gictx, Bc*Tc, H3c, Hc, 150, 150);
  gemm_kernel<true,true><<<dim3(8,15), 256>>>(E, query,   q_Wih,   q_bih,   giq,   Bc*Jc, H3c, Hc, 150, 150);

  gru_scan_kernel<<<64,512>>>(gictx, giq, (const float4*)P_ctx, (const float4*)P_q,
                              ctx_bhh, q_bhh, Hp, Hq);

  gemm_kernel<false,false><<<dim3(3,15), 256>>>(Hq, nullptr, Wq, nullptr, whq,   Bc*Jc, Hc,  Hc, Hc, Hc);
  gemm_kernel<false,false><<<dim3(3,200),256>>>(Hp, nullptr, Wp, gate_b,  preWp, Bc*Tc, Hc,  Hc, Hc, Hc);
  gemm_kernel<true, false><<<dim3(8,200),256>>>(Hp, nullptr, m_Wih,  m_bih,  gixf, Bc*Tc, H3c, Hc, Hc, 2*Hc);
  gemm_kernel<true, false><<<dim3(8,200),256>>>(Hp, nullptr, mr_Wih, mr_bih, gixb, Bc*Tc, H3c, Hc, Hc, 2*Hc);
  gemm_kernel<true, false><<<dim3(8,15), 256>>>(Hq, nullptr, m_Wih  + Hc, nullptr, qpf, Bc*Jc, H3c, Hc, Hc, 2*Hc);
  gemm_kernel<true, false><<<dim3(8,15), 256>>>(Hq, nullptr, mr_Wih + Hc, nullptr, qpb, Bc*Jc, H3c, Hc, Hc, 2*Hc);

  cudaFuncSetAttribute(match_kernel, cudaFuncAttributeMaxDynamicSharedMemorySize,
                       DSMEM_FLOATS*(int)sizeof(float));
  match_kernel<<<64,512, DSMEM_FLOATS*sizeof(float)>>>(
      whq, preWp, gixf, gixb, qpf, qpb, Wr, wv,
      (const float4*)P_m, (const float4*)P_mr, m_bhh, mr_bhh, Hr);

  gemm_kernel<false,false><<<dim3(5,201),256>>>(Hr, nullptr, ptr_W1, nullptr, enc, Bc*TP1c, H2c, H2c, H2c, H2c);

  ptr_kernel<<<32,512>>>(Hr, enc, ptr_W2, ptr_v, d_Wih, d_Whh, d_bih, d_bhh, out);
}

// round 3
// speedup vs baseline: 1.0012x; 1.0012x over previous
#include <cuda_runtime.h>
#include <cuda_bf16.h>
#include <cstdint>

#define Bc   32
#define Tc   400
#define Jc   30
#define Hc   150
#define H2c  300
#define H3c  450
#define TP1c 401
#define KP4  38           // ceil(150/4); k padded to 152 with zeros
#define PACK_ELEMS (KP4*H3c*4)   // 68400 floats per packed weight

// ---------------- device scratch ----------------
__device__ float g_gictx[Bc*Tc*H3c];
__device__ float g_giq  [Bc*Jc*H3c];
__device__ float g_Hp   [Bc*Tc*Hc];
__device__ float g_Hq   [Bc*Jc*Hc];
__device__ float g_whq  [Bc*Jc*Hc];
__device__ float g_preWp[Bc*Tc*Hc];
__device__ float g_gixf [Bc*Tc*H3c];
__device__ float g_gixb [Bc*Tc*H3c];
__device__ float g_qpf  [Bc*Jc*H3c];
__device__ float g_qpb  [Bc*Jc*H3c];
__device__ float g_Hr   [Bc*TP1c*H2c];
__device__ float g_enc  [Bc*TP1c*H2c];
__device__ float g_packs[4*PACK_ELEMS];

// ---------------- fast activations ----------------
__device__ __forceinline__ float fast_ex2(float x){ float y; asm("ex2.approx.f32 %0, %1;" : "=f"(y) : "f"(x)); return y; }
__device__ __forceinline__ float sigm(float x){ return __fdividef(1.f, 1.f + fast_ex2(-1.442695041f*x)); }
__device__ __forceinline__ float tanh_f(float x){
  x = fminf(fmaxf(x, -15.f), 15.f);
  float t = fast_ex2(2.885390082f*x);
  return __fdividef(t - 1.f, t + 1.f);
}

// ---------------- weight transpose-pack: out[(k4*450+n)*4+kk] = W[n*ldw+koff+k4*4+kk] ----------------
__global__ void pack_kernel(const float* __restrict__ W, float* __restrict__ out, int ldw, int koff)
{
  int i = blockIdx.x*blockDim.x + threadIdx.x;
  if (i >= PACK_ELEMS) return;
  int kk = i & 3;
  int n  = (i >> 2) % H3c;
  int k4 = (i >> 2) / H3c;
  int k  = k4*4 + kk;
  out[i] = (k < Hc) ? W[n*ldw + koff + k] : 0.f;
}

// ---------------- GEMM v2: 128x64 tile, 8x4 micro-tile, 256 threads ----------------
// C[m,n] = sum_k Arow(m)[k] * W(n,k) + bias[n]
// TRANSW:  W(n,k) = W[n*ldw + k]    (X @ W^T layout)
// !TRANSW: W(n,k) = W[k*ldw + n]    (X @ W layout)
// GATHER:  Arow(m) = A + idx[m]*lda
template<bool TRANSW, bool GATHER>
__global__ void __launch_bounds__(256) gemm_kernel(
    const float* __restrict__ A, const int* __restrict__ idx,
    const float* __restrict__ W, const float* __restrict__ bias,
    float* __restrict__ C, int M, int N, int K, int lda, int ldw)
{
  __shared__ float As[16][132];   // [k][m], m-tile=128 (+4 pad)
  __shared__ float Bs[16][68];    // [k][n], n-tile=64  (+4 pad)
  int m0 = blockIdx.y*128, n0 = blockIdx.x*64;
  int tid = threadIdx.x;
  int tx = tid & 15, ty = tid >> 4;
  float acc[8][4] = {};

  for (int k0 = 0; k0 < K; k0 += 16) {
    // load A tile: 128x16 = 2048 elems, 8 per thread
    #pragma unroll
    for (int it = 0; it < 8; it++) {
      int li = tid + it*256;
      int m = li >> 4, k = li & 15;
      float v = 0.f;
      int gm = m0 + m, gk = k0 + k;
      if (gm < M && gk < K) {
        int row = GATHER ? idx[gm] : gm;
        v = A[(size_t)row*lda + gk];
      }
      As[k][m] = v;
    }
    // load B tile: 64x16 = 1024 elems, 4 per thread
    #pragma unroll
    for (int it = 0; it < 4; it++) {
      int li = tid + it*256;
      float v = 0.f;
      if (TRANSW) {
        int n = li >> 4, k = li & 15;
        int gn = n0+n, gk = k0+k;
        if (gn < N && gk < K) v = W[(size_t)gn*ldw + gk];
        Bs[k][n] = v;
      } else {
        int k = li >> 6, n = li & 63;
        int gn = n0+n, gk = k0+k;
        if (gn < N && gk < K) v = W[(size_t)gk*ldw + gn];
        Bs[k][n] = v;
      }
    }
    __syncthreads();
    #pragma unroll
    for (int k = 0; k < 16; k++) {
      float4 bv = *reinterpret_cast<const float4*>(&Bs[k][tx*4]);
      float4 a0 = *reinterpret_cast<const float4*>(&As[k][ty*8]);
      float4 a1 = *reinterpret_cast<const float4*>(&As[k][ty*8+4]);
      float am[8] = {a0.x,a0.y,a0.z,a0.w,a1.x,a1.y,a1.z,a1.w};
      #pragma unroll
      for (int i = 0; i < 8; i++) {
        acc[i][0] = fmaf(am[i], bv.x, acc[i][0]);
        acc[i][1] = fmaf(am[i], bv.y, acc[i][1]);
        acc[i][2] = fmaf(am[i], bv.z, acc[i][2]);
        acc[i][3] = fmaf(am[i], bv.w, acc[i][3]);
      }
    }
    __syncthreads();
  }
  #pragma unroll
  for (int i = 0; i < 8; i++) {
    int gm = m0 + ty*8 + i;
    if (gm >= M) continue;
    #pragma unroll
    for (int j = 0; j < 4; j++) {
      int gn = n0 + tx*4 + j;
      if (gn < N) {
        float v = acc[i][j];
        if (bias) v += bias[gn];
        C[(size_t)gm*N + gn] = v;
      }
    }
  }
}

// ---------------- batch-parallel GRU scans (blocks 0..31 ctx, 32..63 query) ----------------
__global__ void __launch_bounds__(512,1) gru_scan_kernel(
    const float* __restrict__ gictx, const float* __restrict__ giq,
    const float4* __restrict__ PctxWhh, const float4* __restrict__ PqWhh,
    const float* __restrict__ ctx_bhh, const float* __restrict__ q_bhh,
    float* __restrict__ Hp, float* __restrict__ Hq)
{
  __shared__ float sh[152];
  __shared__ float sgh[452];
  int tid = threadIdx.x;
  int isq = blockIdx.x >> 5;
  int b   = blockIdx.x & 31;
  const float*  gi   = isq ? (giq + (size_t)b*Jc*H3c) : (gictx + (size_t)b*Tc*H3c);
  const float4* Wp4  = isq ? PqWhh : PctxWhh;
  const float*  bhh  = isq ? q_bhh : ctx_bhh;
  float*        outp = isq ? (Hq + (size_t)b*Jc*Hc) : (Hp + (size_t)b*Tc*Hc);
  int Tlen = isq ? Jc : Tc;

  float my_b = (tid < H3c) ? bhh[tid] : 0.f;
  if (tid < 152) sh[tid] = 0.f;
  __syncthreads();

  for (int t = 0; t < Tlen; t++) {
    if (tid < H3c) {
      float acc = my_b;
      const float4* wr = Wp4 + tid;
      #pragma unroll
      for (int k4 = 0; k4 < KP4; k4++) {
        float4 h4 = *reinterpret_cast<const float4*>(sh + k4*4);
        float4 w4 = wr[(size_t)k4*H3c];
        acc = fmaf(h4.x,w4.x,fmaf(h4.y,w4.y,fmaf(h4.z,w4.z,fmaf(h4.w,w4.w,acc))));
      }
      sgh[tid] = acc;
    }
    __syncthreads();
    if (tid < Hc) {
      const float* gr = gi + (size_t)t*H3c;
      float r  = sigm(gr[tid]        + sgh[tid]);
      float z  = sigm(gr[Hc + tid]   + sgh[Hc + tid]);
      float nn = tanh_f(gr[2*Hc+tid] + r*sgh[2*Hc + tid]);
      float hn = nn + z*(sh[tid] - nn);
      sh[tid] = hn;
      outp[(size_t)t*Hc + tid] = hn;
    }
    __syncthreads();
  }
}

// ---------------- match scans (blocks 0..31 fwd, 32..63 rev) ----------------
// dynamic smem: sWrT[150*164] | sWhq[30*150] | sQP[30*450]
#define SWRT_STRIDE 164
#define DSMEM_FLOATS (Hc*SWRT_STRIDE + Jc*Hc + Jc*H3c)  // 24600+4500+13500 = 42600

__global__ void __launch_bounds__(512,1) match_kernel(
    const float* __restrict__ whq,  const float* __restrict__ preWp,
    const float* __restrict__ gixf, const float* __restrict__ gixb,
    const float* __restrict__ qpf,  const float* __restrict__ qpb,
    const float* __restrict__ Wr,   const float* __restrict__ wvec,
    const float4* __restrict__ WhPf, const float4* __restrict__ WhPb,
    const float* __restrict__ m_bhh, const float* __restrict__ mr_bhh,
    float* __restrict__ Hr)
{
  extern __shared__ float dsm[];
  float* sWrT = dsm;                          // [150][164] transposed Wr, padded rows
  float* sWhq = dsm + Hc*SWRT_STRIDE;         // [30][150]
  float* sQP  = sWhq + Jc*Hc;                 // [30][450]
  __shared__ float sw [152];
  __shared__ float sh [152];
  __shared__ float se [152];
  __shared__ float sgi[452];
  __shared__ float sgh[452];
  __shared__ float sS [32];
  __shared__ float sA [32];

  int tid = threadIdx.x;
  int dir = blockIdx.x >> 5;
  int b   = blockIdx.x & 31;

  const float*  gix = (dir ? gixb : gixf) + (size_t)b*Tc*H3c;
  const float*  qp  = (dir ? qpb  : qpf)  + (size_t)b*Jc*H3c;
  const float4* WhP = dir ? WhPb : WhPf;
  const float*  bhh = dir ? mr_bhh : m_bhh;
  const float*  preW = preWp + (size_t)b*Tc*Hc;

  for (int i = tid; i < Hc*Hc; i += 512) { int j = i/Hc, k = i%Hc; sWrT[k*SWRT_STRIDE + j] = Wr[i]; }
  for (int i = tid; i < Jc*Hc; i += 512) sWhq[i] = whq[(size_t)b*Jc*Hc + i];
  for (int i = tid; i < Jc*H3c; i += 512) sQP[i] = qp[i];
  if (tid < 152) { sw[tid] = (tid < Hc) ? wvec[tid] : 0.f; sh[tid] = 0.f; }
  if (tid < Hc)  { sWrT[tid*SWRT_STRIDE + 150] = 0.f; sWrT[tid*SWRT_STRIDE + 151] = 0.f;
                   Hr[((size_t)b*TP1c)*H2c + dir*Hc + tid] = 0.f; }
  float my_bhh = (tid < H3c) ? bhh[tid] : 0.f;
  __syncthreads();

  for (int step = 0; step < Tc; step++) {
    int t = dir ? (Tc-1-step) : step;

    // S1: gh = bhh + h@Whh^T (L2 stream) CONCURRENT with e = preWp[t] + h@Wr (smem)
    if (tid < H3c) {
      float gh = my_bhh;
      const float4* wh = WhP + tid;
      #pragma unroll
      for (int k4 = 0; k4 < KP4; k4++) {
        float4 h4 = *reinterpret_cast<const float4*>(sh + k4*4);
        float4 w4 = wh[(size_t)k4*H3c];
        gh = fmaf(h4.x,w4.x,fmaf(h4.y,w4.y,fmaf(h4.z,w4.z,fmaf(h4.w,w4.w,gh))));
      }
      sgh[tid] = gh;
    }
    if (tid < Hc) {
      float acc = preW[(size_t)t*Hc + tid];
      const float4* row = reinterpret_cast<const float4*>(sWrT + tid*SWRT_STRIDE);
      #pragma unroll
      for (int k4 = 0; k4 < KP4; k4++) {
        float4 h4 = *reinterpret_cast<const float4*>(sh + k4*4);
        float4 w4 = row[k4];
        acc = fmaf(h4.x,w4.x,fmaf(h4.y,w4.y,fmaf(h4.z,w4.z,fmaf(h4.w,w4.w,acc))));
      }
      se[tid] = acc;
    }
    __syncthreads();

    // S2: s_j = sum_k tanh(whq[j,k] + e[k]) * w[k]   (attn_bias softmax-invariant)
    {
      int wid = tid >> 5, lane = tid & 31;
      if (wid < 15) {
        #pragma unroll
        for (int jj = 0; jj < 2; jj++) {
          int j = wid*2 + jj;
          float p = 0.f;
          for (int k = lane; k < Hc; k += 32)
            p = fmaf(tanh_f(sWhq[j*Hc + k] + se[k]), sw[k], p);
          #pragma unroll
          for (int o = 16; o; o >>= 1) p += __shfl_xor_sync(0xffffffffu, p, o);
          if (lane == 0) sS[j] = p;
        }
      }
    }
    __syncthreads();

    // S3: softmax over J=30 (warp 0); other threads prefetch gix[t] into regs
    float gival = 0.f;
    if (tid < H3c) gival = gix[(size_t)t*H3c + tid];
    if (tid < 32) {
      float v = (tid < Jc) ? sS[tid] : -1e30f;
      float m = v;
      #pragma unroll
      for (int o = 16; o; o >>= 1) m = fmaxf(m, __shfl_xor_sync(0xffffffffu, m, o));
      float e = (tid < Jc) ? fast_ex2(1.442695041f*(v - m)) : 0.f;
      float su = e;
      #pragma unroll
      for (int o = 16; o; o >>= 1) su += __shfl_xor_sync(0xffffffffu, su, o);
      sA[tid] = e * __fdividef(1.f, su);
    }
    __syncthreads();

    // S4: gi = gix[t] + sum_j a_j * qproj[j]
    if (tid < H3c) {
      float gi = gival;
      #pragma unroll
      for (int j = 0; j < Jc; j++) gi = fmaf(sA[j], sQP[j*H3c + tid], gi);
      sgi[tid] = gi;
    }
    __syncthreads();

    // S5: GRU update + write Hr (storage index = scan step)
    if (tid < Hc) {
      float r  = sigm(sgi[tid] + sgh[tid]);
      float z  = sigm(sgi[Hc+tid] + sgh[Hc+tid]);
      float nn = tanh_f(sgi[2*Hc+tid] + r*sgh[2*Hc+tid]);
      float hn = nn + z*(sh[tid] - nn);
      sh[tid] = hn;
      Hr[((size_t)b*TP1c + 1 + step)*H2c + dir*Hc + tid] = hn;
    }
    __syncthreads();
  }
}

// ---------------- pointer decoder (32 blocks, 2 steps) ----------------
__global__ void __launch_bounds__(512,1) ptr_kernel(
    const float* __restrict__ Hr, const float* __restrict__ enc,
    const float* __restrict__ ptr_W2, const float* __restrict__ ptr_v,
    const float* __restrict__ d_Wih, const float* __restrict__ d_Whh,
    const float* __restrict__ d_bih, const float* __restrict__ d_bhh,
    float* __restrict__ out)
{
  __shared__ float sh[H2c], shw[H2c], sc[H2c], sa[TP1c + 3], sgi[900], sgh[900];
  __shared__ float red[2];
  int b = blockIdx.x, tid = threadIdx.x;
  int wid = tid >> 5, lane = tid & 31;
  const float* encb = enc + (size_t)b*TP1c*H2c;
  const float* Hrb  = Hr  + (size_t)b*TP1c*H2c;
  if (tid < H2c) sh[tid] = 0.f;
  __syncthreads();

  for (int step = 0; step < 2; step++) {
    // hw2 = h @ ptr_W2
    if (tid < H2c) {
      float a = 0.f;
      for (int j = 0; j < H2c; j++) a = fmaf(sh[j], ptr_W2[(size_t)j*H2c + tid], a);
      shw[tid] = a;
    }
    __syncthreads();
    // scores over T+1 positions
    for (int t = wid; t < TP1c; t += 16) {
      float p = 0.f;
      const float* er = encb + (size_t)t*H2c;
      for (int k = lane; k < H2c; k += 32) p = fmaf(tanh_f(er[k] + shw[k]), ptr_v[k], p);
      #pragma unroll
      for (int o = 16; o; o >>= 1) p += __shfl_xor_sync(0xffffffffu, p, o);
      if (lane == 0) sa[t] = p;
    }
    __syncthreads();
    // softmax over 401
    if (tid < 32) {
      float m = -1e30f;
      for (int t = lane; t < TP1c; t += 32) m = fmaxf(m, sa[t]);
      #pragma unroll
      for (int o = 16; o; o >>= 1) m = fmaxf(m, __shfl_xor_sync(0xffffffffu, m, o));
      if (lane == 0) red[0] = m;
    }
    __syncthreads();
    float mm = red[0];
    for (int t = tid; t < TP1c; t += 512) sa[t] = fast_ex2(1.442695041f*(sa[t] - mm));
    __syncthreads();
    if (tid < 32) {
      float s = 0.f;
      for (int t = lane; t < TP1c; t += 32) s += sa[t];
      #pragma unroll
      for (int o = 16; o; o >>= 1) s += __shfl_xor_sync(0xffffffffu, s, o);
      if (lane == 0) red[1] = __fdividef(1.f, s);
    }
    __syncthreads();
    float inv = red[1];
    for (int t = tid; t < TP1c; t += 512) {
      float a = sa[t] * inv;
      sa[t] = a;
      out[((size_t)b*2 + step)*TP1c + t] = a;
    }
    __syncthreads();
    // c = a @ Hr
    if (tid < H2c) {
      float a = 0.f;
      for (int t = 0; t < TP1c; t++) a = fmaf(sa[t], Hrb[(size_t)t*H2c + tid], a);
      sc[tid] = a;
    }
    __syncthreads();
    // decoder GRU (hidden 300, gates 900)
    for (int n = tid; n < 900; n += 512) {
      float gi = d_bih[n], gh = d_bhh[n];
      const float* wi = d_Wih + (size_t)n*H2c;
      const float* wh = d_Whh + (size_t)n*H2c;
      for (int k = 0; k < H2c; k++) { gi = fmaf(sc[k], wi[k], gi); gh = fmaf(sh[k], wh[k], gh); }
      sgi[n] = gi; sgh[n] = gh;
    }
    __syncthreads();
    if (tid < H2c) {
      float r  = sigm(sgi[tid] + sgh[tid]);
      float z  = sigm(sgi[H2c+tid] + sgh[H2c+tid]);
      float nn = tanh_f(sgi[2*H2c+tid] + r*sgh[2*H2c+tid]);
      sh[tid] = nn + z*(sh[tid] - nn);
    }
    __syncthreads();
  }
}

// ---------------- host ----------------
static void* sym(const void* s) { void* p = nullptr; cudaGetSymbolAddress(&p, s); return p; }

extern "C" void kernel_launch(void* const* d_in, const int* in_sizes, int n_in,
                              void* d_out, int out_size)
{
  const int*   context = (const int*)  d_in[0];
  const int*   query   = (const int*)  d_in[1];
  const float* E       = (const float*)d_in[2];
  const float* ctx_Wih = (const float*)d_in[3];
  const float* ctx_Whh = (const float*)d_in[4];
  const float* ctx_bih = (const float*)d_in[5];
  const float* ctx_bhh = (const float*)d_in[6];
  const float* q_Wih   = (const float*)d_in[7];
  const float* q_Whh   = (const float*)d_in[8];
  const float* q_bih   = (const float*)d_in[9];
  const float* q_bhh   = (const float*)d_in[10];
  const float* Wq      = (const float*)d_in[11];
  const float* Wp      = (const float*)d_in[12];
  const float* Wr      = (const float*)d_in[13];
  const float* wv      = (const float*)d_in[14];
  const float* gate_b  = (const float*)d_in[15];
  // d_in[16] = attn_bias (scalar, softmax-invariant -> unused)
  const float* m_Wih   = (const float*)d_in[17];
  const float* m_Whh   = (const float*)d_in[18];
  const float* m_bih   = (const float*)d_in[19];
  const float* m_bhh   = (const float*)d_in[20];
  const float* mr_Wih  = (const float*)d_in[21];
  const float* mr_Whh  = (const float*)d_in[22];
  const float* mr_bih  = (const float*)d_in[23];
  const float* mr_bhh  = (const float*)d_in[24];
  const float* ptr_W1  = (const float*)d_in[25];
  const float* ptr_W2  = (const float*)d_in[26];
  const float* ptr_v   = (const float*)d_in[27];
  const float* d_Wih   = (const float*)d_in[28];
  const float* d_Whh   = (const float*)d_in[29];
  const float* d_bih   = (const float*)d_in[30];
  const float* d_bhh   = (const float*)d_in[31];
  float* out = (float*)d_out;

  float* gictx = (float*)sym(g_gictx);
  float* giq   = (float*)sym(g_giq);
  float* Hp    = (float*)sym(g_Hp);
  float* Hq    = (float*)sym(g_Hq);
  float* whq   = (float*)sym(g_whq);
  float* preWp = (float*)sym(g_preWp);
  float* gixf  = (float*)sym(g_gixf);
  float* gixb  = (float*)sym(g_gixb);
  float* qpf   = (float*)sym(g_qpf);
  float* qpb   = (float*)sym(g_qpb);
  float* Hr    = (float*)sym(g_Hr);
  float* enc   = (float*)sym(g_enc);
  float* packs = (float*)sym(g_packs);
  float* P_ctx = packs + 0*PACK_ELEMS;
  float* P_q   = packs + 1*PACK_ELEMS;
  float* P_m   = packs + 2*PACK_ELEMS;
  float* P_mr  = packs + 3*PACK_ELEMS;

  int pk_grid = (PACK_ELEMS + 255)/256;
  pack_kernel<<<pk_grid,256>>>(ctx_Whh, P_ctx, Hc, 0);
  pack_kernel<<<pk_grid,256>>>(q_Whh,   P_q,   Hc, 0);
  pack_kernel<<<pk_grid,256>>>(m_Whh,   P_m,   Hc, 0);
  pack_kernel<<<pk_grid,256>>>(mr_Whh,  P_mr,  Hc, 0);

  // gi projections of embedded tokens
  gemm_kernel<true,true><<<dim3(8,100),256>>>(E, context, ctx_Wih, ctx_bih, gictx, Bc*Tc, H3c, Hc, 150, 150);
  gemm_kernel<true,true><<<dim3(8,8),  256>>>(E, query,   q_Wih,   q_bih,   giq,   Bc*Jc, H3c, Hc, 150, 150);

  gru_scan_kernel<<<64,512>>>(gictx, giq, (const float4*)P_ctx, (const float4*)P_q,
                              ctx_bhh, q_bhh, Hp, Hq);

  gemm_kernel<false,false><<<dim3(3,8),  256>>>(Hq, nullptr, Wq, nullptr, whq,   Bc*Jc, Hc,  Hc, Hc, Hc);
  gemm_kernel<false,false><<<dim3(3,100),256>>>(Hp, nullptr, Wp, gate_b,  preWp, Bc*Tc, Hc,  Hc, Hc, Hc);
  gemm_kernel<true, false><<<dim3(8,100),256>>>(Hp, nullptr, m_Wih,  m_bih,  gixf, Bc*Tc, H3c, Hc, Hc, 2*Hc);
  gemm_kernel<true, false><<<dim3(8,100),256>>>(Hp, nullptr, mr_Wih, mr_bih, gixb, Bc*Tc, H3c, Hc, Hc, 2*Hc);
  gemm_kernel<true, false><<<dim3(8,8),  256>>>(Hq, nullptr, m_Wih  + Hc, nullptr, qpf, Bc*Jc, H3c, Hc, Hc, 2*Hc);
  gemm_kernel<true, false><<<dim3(8,8),  256>>>(Hq, nullptr, mr_Wih + Hc, nullptr, qpb, Bc*Jc, H3c, Hc, Hc, 2*Hc);

  cudaFuncSetAttribute(match_kernel, cudaFuncAttributeMaxDynamicSharedMemorySize,
                       DSMEM_FLOATS*(int)sizeof(float));
  match_kernel<<<64,512, DSMEM_FLOATS*sizeof(float)>>>(
      whq, preWp, gixf, gixb, qpf, qpb, Wr, wv,
      (const float4*)P_m, (const float4*)P_mr, m_bhh, mr_bhh, Hr);

  gemm_kernel<false,false><<<dim3(5,101),256>>>(Hr, nullptr, ptr_W1, nullptr, enc, Bc*TP1c, H2c, H2c, H2c, H2c);

  ptr_kernel<<<32,512>>>(Hr, enc, ptr_W2, ptr_v, d_Wih, d_Whh, d_bih, d_bhh, out);
}

// round 4
// speedup vs baseline: 1.2641x; 1.2626x over previous
#include <cuda_runtime.h>
#include <cuda_bf16.h>
#include <cstdint>

#define Bc   32
#define Tc   400
#define Jc   30
#define Hc   150
#define H2c  300
#define H3c  450
#define TP1c 401
#define K8c  19                  // ceil(152/8) k-chunks of 8 (k padded to 152)
#define PACKB_ELEMS (K8c*H3c*8)  // 68400 bf16 per packed weight

// ---------------- device scratch ----------------
__device__ float g_gictx[Bc*Tc*H3c];
__device__ float g_giq  [Bc*Jc*H3c];
__device__ float g_Hp   [Bc*Tc*Hc];
__device__ float g_Hq   [Bc*Jc*Hc];
__device__ float g_whq  [Bc*Jc*Hc];
__device__ float g_preWp[Bc*Tc*Hc];
__device__ float g_gixf [Bc*Tc*H3c];
__device__ float g_gixb [Bc*Tc*H3c];
__device__ float g_qpf  [Bc*Jc*H3c];
__device__ float g_qpb  [Bc*Jc*H3c];
__device__ float g_Hr   [Bc*TP1c*H2c];
__device__ float g_enc  [Bc*TP1c*H2c];
__device__ __align__(16) __nv_bfloat16 g_packsb[4*PACKB_ELEMS];

// ---------------- fast activations ----------------
__device__ __forceinline__ float fast_ex2(float x){ float y; asm("ex2.approx.f32 %0, %1;" : "=f"(y) : "f"(x)); return y; }
__device__ __forceinline__ float sigm(float x){ return __fdividef(1.f, 1.f + fast_ex2(-1.442695041f*x)); }
__device__ __forceinline__ float tanh_f(float x){
  x = fminf(fmaxf(x, -15.f), 15.f);
  float t = fast_ex2(2.885390082f*x);
  return __fdividef(t - 1.f, t + 1.f);
}

// 8-wide bf16 dot step: w holds 8 bf16 (k..k+7), h0/h1 the matching fp32 h values
__device__ __forceinline__ float fma8(uint4 w, float4 h0, float4 h1, float acc){
  float2 w0 = __bfloat1622float2(*reinterpret_cast<const __nv_bfloat162*>(&w.x));
  float2 w1 = __bfloat1622float2(*reinterpret_cast<const __nv_bfloat162*>(&w.y));
  float2 w2 = __bfloat1622float2(*reinterpret_cast<const __nv_bfloat162*>(&w.z));
  float2 w3 = __bfloat1622float2(*reinterpret_cast<const __nv_bfloat162*>(&w.w));
  acc = fmaf(h0.x,w0.x,acc); acc = fmaf(h0.y,w0.y,acc);
  acc = fmaf(h0.z,w1.x,acc); acc = fmaf(h0.w,w1.y,acc);
  acc = fmaf(h1.x,w2.x,acc); acc = fmaf(h1.y,w2.y,acc);
  acc = fmaf(h1.z,w3.x,acc); acc = fmaf(h1.w,w3.y,acc);
  return acc;
}

// ---------------- bf16 transpose-pack: out[(k8*450+n)*8+kk] = bf16(W[n*150 + k8*8+kk]) ----------------
__global__ void pack_bf16_kernel(const float* __restrict__ W, __nv_bfloat16* __restrict__ out)
{
  int i = blockIdx.x*blockDim.x + threadIdx.x;
  if (i >= PACKB_ELEMS) return;
  int kk = i & 7;
  int rest = i >> 3;
  int n  = rest % H3c;
  int k8 = rest / H3c;
  int k  = k8*8 + kk;
  out[i] = __float2bfloat16((k < Hc) ? W[n*Hc + k] : 0.f);
}

// ---------------- GEMM: 128x64 tile, 8x4 micro-tile, 256 threads ----------------
template<bool TRANSW, bool GATHER>
__global__ void __launch_bounds__(256) gemm_kernel(
    const float* __restrict__ A, const int* __restrict__ idx,
    const float* __restrict__ W, const float* __restrict__ bias,
    float* __restrict__ C, int M, int N, int K, int lda, int ldw)
{
  __shared__ float As[16][132];
  __shared__ float Bs[16][68];
  int m0 = blockIdx.y*128, n0 = blockIdx.x*64;
  int tid = threadIdx.x;
  int tx = tid & 15, ty = tid >> 4;
  float acc[8][4] = {};

  for (int k0 = 0; k0 < K; k0 += 16) {
    #pragma unroll
    for (int it = 0; it < 8; it++) {
      int li = tid + it*256;
      int m = li >> 4, k = li & 15;
      float v = 0.f;
      int gm = m0 + m, gk = k0 + k;
      if (gm < M && gk < K) {
        int row = GATHER ? idx[gm] : gm;
        v = A[(size_t)row*lda + gk];
      }
      As[k][m] = v;
    }
    #pragma unroll
    for (int it = 0; it < 4; it++) {
      int li = tid + it*256;
      float v = 0.f;
      if (TRANSW) {
        int n = li >> 4, k = li & 15;
        int gn = n0+n, gk = k0+k;
        if (gn < N && gk < K) v = W[(size_t)gn*ldw + gk];
        Bs[k][n] = v;
      } else {
        int k = li >> 6, n = li & 63;
        int gn = n0+n, gk = k0+k;
        if (gn < N && gk < K) v = W[(size_t)gk*ldw + gn];
        Bs[k][n] = v;
      }
    }
    __syncthreads();
    #pragma unroll
    for (int k = 0; k < 16; k++) {
      float4 bv = *reinterpret_cast<const float4*>(&Bs[k][tx*4]);
      float4 a0 = *reinterpret_cast<const float4*>(&As[k][ty*8]);
      float4 a1 = *reinterpret_cast<const float4*>(&As[k][ty*8+4]);
      float am[8] = {a0.x,a0.y,a0.z,a0.w,a1.x,a1.y,a1.z,a1.w};
      #pragma unroll
      for (int i = 0; i < 8; i++) {
        acc[i][0] = fmaf(am[i], bv.x, acc[i][0]);
        acc[i][1] = fmaf(am[i], bv.y, acc[i][1]);
        acc[i][2] = fmaf(am[i], bv.z, acc[i][2]);
        acc[i][3] = fmaf(am[i], bv.w, acc[i][3]);
      }
    }
    __syncthreads();
  }
  #pragma unroll
  for (int i = 0; i < 8; i++) {
    int gm = m0 + ty*8 + i;
    if (gm >= M) continue;
    #pragma unroll
    for (int j = 0; j < 4; j++) {
      int gn = n0 + tx*4 + j;
      if (gn < N) {
        float v = acc[i][j];
        if (bias) v += bias[gn];
        C[(size_t)gm*N + gn] = v;
      }
    }
  }
}

// ---------------- batch-parallel GRU scans (blocks 0..31 ctx, 32..63 query), bf16 weights ----------------
__global__ void __launch_bounds__(512,1) gru_scan_kernel(
    const float* __restrict__ gictx, const float* __restrict__ giq,
    const uint4* __restrict__ PctxWhh, const uint4* __restrict__ PqWhh,
    const float* __restrict__ ctx_bhh, const float* __restrict__ q_bhh,
    float* __restrict__ Hp, float* __restrict__ Hq)
{
  __shared__ float sh[152];
  __shared__ float sgh[452];
  int tid = threadIdx.x;
  int isq = blockIdx.x >> 5;
  int b   = blockIdx.x & 31;
  const float* gi   = isq ? (giq + (size_t)b*Jc*H3c) : (gictx + (size_t)b*Tc*H3c);
  const uint4* Wp4  = isq ? PqWhh : PctxWhh;
  const float* bhh  = isq ? q_bhh : ctx_bhh;
  float*       outp = isq ? (Hq + (size_t)b*Jc*Hc) : (Hp + (size_t)b*Tc*Hc);
  int Tlen = isq ? Jc : Tc;

  float my_b = (tid < H3c) ? bhh[tid] : 0.f;
  if (tid < 152) sh[tid] = 0.f;
  __syncthreads();

  for (int t = 0; t < Tlen; t++) {
    if (tid < H3c) {
      float acc = my_b;
      const uint4* wr = Wp4 + tid;
      #pragma unroll
      for (int k8 = 0; k8 < K8c; k8++) {
        uint4 w = wr[(size_t)k8*H3c];
        float4 h0 = *reinterpret_cast<const float4*>(sh + k8*8);
        float4 h1 = *reinterpret_cast<const float4*>(sh + k8*8 + 4);
        acc = fma8(w, h0, h1, acc);
      }
      sgh[tid] = acc;
    }
    __syncthreads();
    if (tid < Hc) {
      const float* gr = gi + (size_t)t*H3c;
      float r  = sigm(gr[tid]        + sgh[tid]);
      float z  = sigm(gr[Hc + tid]   + sgh[Hc + tid]);
      float nn = tanh_f(gr[2*Hc+tid] + r*sgh[2*Hc + tid]);
      float hn = nn + z*(sh[tid] - nn);
      sh[tid] = hn;
      outp[(size_t)t*Hc + tid] = hn;
    }
    __syncthreads();
  }
}

// ---------------- match scans (blocks 0..31 fwd, 32..63 rev), 640 threads ----------------
// dynamic smem: sWhq fp32 [30*150] | sQP fp32 [30*450] | sWrTb bf16 [150*152]
#define MATCH_THREADS 640
#define EBASE 480
#define DSMEM_BYTES (Jc*Hc*4 + Jc*H3c*4 + Hc*152*2)   // 18000+54000+45600 = 117600

__global__ void __launch_bounds__(MATCH_THREADS,1) match_kernel(
    const float* __restrict__ whq,  const float* __restrict__ preWp,
    const float* __restrict__ gixf, const float* __restrict__ gixb,
    const float* __restrict__ qpf,  const float* __restrict__ qpb,
    const float* __restrict__ Wr,   const float* __restrict__ wvec,
    const uint4* __restrict__ WhPf, const uint4* __restrict__ WhPb,
    const float* __restrict__ m_bhh, const float* __restrict__ mr_bhh,
    float* __restrict__ Hr)
{
  extern __shared__ float dsm[];
  float* sWhq = dsm;                               // [30][150]
  float* sQP  = dsm + Jc*Hc;                       // [30][450]
  __nv_bfloat16* sWrTb = (__nv_bfloat16*)(dsm + Jc*Hc + Jc*H3c);  // [150][152], byte 72000
  __shared__ float sw [152];
  __shared__ float sh [152];
  __shared__ float se [152];
  __shared__ float sgh[452];
  __shared__ float sS [32];
  __shared__ float sA [32];

  int tid = threadIdx.x;
  int dir = blockIdx.x >> 5;
  int b   = blockIdx.x & 31;

  const float* gix = (dir ? gixb : gixf) + (size_t)b*Tc*H3c;
  const float* qp  = (dir ? qpb  : qpf)  + (size_t)b*Jc*H3c;
  const uint4* WhP = dir ? WhPb : WhPf;
  const float* bhh = dir ? mr_bhh : m_bhh;
  const float* preW = preWp + (size_t)b*Tc*Hc;

  // preamble
  for (int i = tid; i < Hc*152; i += MATCH_THREADS) {
    int n = i / 152, k = i % 152;
    sWrTb[n*152 + k] = __float2bfloat16((k < Hc) ? Wr[k*Hc + n] : 0.f);
  }
  for (int i = tid; i < Jc*Hc; i += MATCH_THREADS) sWhq[i] = whq[(size_t)b*Jc*Hc + i];
  for (int i = tid; i < Jc*H3c; i += MATCH_THREADS) sQP[i] = qp[i];
  if (tid < 152) { sw[tid] = (tid < Hc) ? wvec[tid] : 0.f; sh[tid] = 0.f; }
  if (tid < Hc)  Hr[((size_t)b*TP1c)*H2c + dir*Hc + tid] = 0.f;
  float my_bhh = (tid < H3c) ? bhh[tid] : 0.f;
  __syncthreads();

  for (int step = 0; step < Tc; step++) {
    int t = dir ? (Tc-1-step) : step;

    // prefetch per-step inputs (independent of S1)
    float g0=0.f, g1=0.f, g2=0.f;
    if (tid < Hc) {
      const float* gr = gix + (size_t)t*H3c;
      g0 = gr[tid]; g1 = gr[Hc+tid]; g2 = gr[2*Hc+tid];
    }
    float pw = 0.f;
    if (tid >= EBASE && tid < EBASE+Hc) pw = preW[(size_t)t*Hc + (tid-EBASE)];

    // S1a: gh = bhh + h@Whh^T (bf16 global, threads 0..449)
    if (tid < H3c) {
      float gh = my_bhh;
      const uint4* wh = WhP + tid;
      #pragma unroll
      for (int k8 = 0; k8 < K8c; k8++) {
        uint4 w = wh[(size_t)k8*H3c];
        float4 h0 = *reinterpret_cast<const float4*>(sh + k8*8);
        float4 h1 = *reinterpret_cast<const float4*>(sh + k8*8 + 4);
        gh = fma8(w, h0, h1, gh);
      }
      sgh[tid] = gh;
    }
    // S1b: e = preWp[t] + h@Wr (bf16 smem, threads 480..629)
    if (tid >= EBASE && tid < EBASE+Hc) {
      int n = tid - EBASE;
      float acc = pw;
      const uint4* row = reinterpret_cast<const uint4*>(sWrTb + n*152);
      #pragma unroll
      for (int k8 = 0; k8 < K8c; k8++) {
        uint4 w = row[k8];
        float4 h0 = *reinterpret_cast<const float4*>(sh + k8*8);
        float4 h1 = *reinterpret_cast<const float4*>(sh + k8*8 + 4);
        acc = fma8(w, h0, h1, acc);
      }
      se[n] = acc;
    }
    __syncthreads();

    // S2: s_j = sum_k tanh(whq[j,k] + e[k]) * w[k]
    {
      int wid = tid >> 5, lane = tid & 31;
      if (wid < 15) {
        #pragma unroll
        for (int jj = 0; jj < 2; jj++) {
          int j = wid*2 + jj;
          float p = 0.f;
          for (int k = lane; k < Hc; k += 32)
            p = fmaf(tanh_f(sWhq[j*Hc + k] + se[k]), sw[k], p);
          #pragma unroll
          for (int o = 16; o; o >>= 1) p += __shfl_xor_sync(0xffffffffu, p, o);
          if (lane == 0) sS[j] = p;
        }
      }
    }
    __syncthreads();

    // S3: softmax over J=30 (warp 0)
    if (tid < 32) {
      float v = (tid < Jc) ? sS[tid] : -1e30f;
      float m = v;
      #pragma unroll
      for (int o = 16; o; o >>= 1) m = fmaxf(m, __shfl_xor_sync(0xffffffffu, m, o));
      float e = (tid < Jc) ? fast_ex2(1.442695041f*(v - m)) : 0.f;
      float su = e;
      #pragma unroll
      for (int o = 16; o; o >>= 1) su += __shfl_xor_sync(0xffffffffu, su, o);
      sA[tid] = e * __fdividef(1.f, su);
    }
    __syncthreads();

    // S4+S5 fused: gi = gix + a@qproj (per-gate), GRU update, write Hr
    if (tid < Hc) {
      float gr_ = g0, gz_ = g1, gn_ = g2;
      #pragma unroll
      for (int j = 0; j < Jc; j++) {
        float a = sA[j];
        gr_ = fmaf(a, sQP[j*H3c + tid],        gr_);
        gz_ = fmaf(a, sQP[j*H3c + Hc + tid],   gz_);
        gn_ = fmaf(a, sQP[j*H3c + 2*Hc + tid], gn_);
      }
      float r  = sigm(gr_ + sgh[tid]);
      float z  = sigm(gz_ + sgh[Hc+tid]);
      float nn = tanh_f(gn_ + r*sgh[2*Hc+tid]);
      float hn = nn + z*(sh[tid] - nn);
      sh[tid] = hn;
      Hr[((size_t)b*TP1c + 1 + step)*H2c + dir*Hc + tid] = hn;
    }
    __syncthreads();
  }
}

// ---------------- pointer decoder (32 blocks, 2 steps) ----------------
__global__ void __launch_bounds__(512,1) ptr_kernel(
    const float* __restrict__ Hr, const float* __restrict__ enc,
    const float* __restrict__ ptr_W2, const float* __restrict__ ptr_v,
    const float* __restrict__ d_Wih, const float* __restrict__ d_Whh,
    const float* __restrict__ d_bih, const float* __restrict__ d_bhh,
    float* __restrict__ out)
{
  __shared__ float sh[H2c], shw[H2c], sc[H2c], sa[TP1c + 3], sgi[900], sgh[900];
  __shared__ float red[2];
  int b = blockIdx.x, tid = threadIdx.x;
  int wid = tid >> 5, lane = tid & 31;
  const float* encb = enc + (size_t)b*TP1c*H2c;
  const float* Hrb  = Hr  + (size_t)b*TP1c*H2c;
  if (tid < H2c) sh[tid] = 0.f;
  __syncthreads();

  for (int step = 0; step < 2; step++) {
    if (tid < H2c) {
      float a = 0.f;
      for (int j = 0; j < H2c; j++) a = fmaf(sh[j], ptr_W2[(size_t)j*H2c + tid], a);
      shw[tid] = a;
    }
    __syncthreads();
    for (int t = wid; t < TP1c; t += 16) {
      float p = 0.f;
      const float* er = encb + (size_t)t*H2c;
      for (int k = lane; k < H2c; k += 32) p = fmaf(tanh_f(er[k] + shw[k]), ptr_v[k], p);
      #pragma unroll
      for (int o = 16; o; o >>= 1) p += __shfl_xor_sync(0xffffffffu, p, o);
      if (lane == 0) sa[t] = p;
    }
    __syncthreads();
    if (tid < 32) {
      float m = -1e30f;
      for (int t = lane; t < TP1c; t += 32) m = fmaxf(m, sa[t]);
      #pragma unroll
      for (int o = 16; o; o >>= 1) m = fmaxf(m, __shfl_xor_sync(0xffffffffu, m, o));
      if (lane == 0) red[0] = m;
    }
    __syncthreads();
    float mm = red[0];
    for (int t = tid; t < TP1c; t += 512) sa[t] = fast_ex2(1.442695041f*(sa[t] - mm));
    __syncthreads();
    if (tid < 32) {
      float s = 0.f;
      for (int t = lane; t < TP1c; t += 32) s += sa[t];
      #pragma unroll
      for (int o = 16; o; o >>= 1) s += __shfl_xor_sync(0xffffffffu, s, o);
      if (lane == 0) red[1] = __fdividef(1.f, s);
    }
    __syncthreads();
    float inv = red[1];
    for (int t = tid; t < TP1c; t += 512) {
      float a = sa[t] * inv;
      sa[t] = a;
      out[((size_t)b*2 + step)*TP1c + t] = a;
    }
    __syncthreads();
    if (tid < H2c) {
      float a = 0.f;
      for (int t = 0; t < TP1c; t++) a = fmaf(sa[t], Hrb[(size_t)t*H2c + tid], a);
      sc[tid] = a;
    }
    __syncthreads();
    for (int n = tid; n < 900; n += 512) {
      float gi = d_bih[n], gh = d_bhh[n];
      const float* wi = d_Wih + (size_t)n*H2c;
      const float* wh = d_Whh + (size_t)n*H2c;
      for (int k = 0; k < H2c; k++) { gi = fmaf(sc[k], wi[k], gi); gh = fmaf(sh[k], wh[k], gh); }
      sgi[n] = gi; sgh[n] = gh;
    }
    __syncthreads();
    if (tid < H2c) {
      float r  = sigm(sgi[tid] + sgh[tid]);
      float z  = sigm(sgi[H2c+tid] + sgh[H2c+tid]);
      float nn = tanh_f(sgi[2*H2c+tid] + r*sgh[2*H2c+tid]);
      sh[tid] = nn + z*(sh[tid] - nn);
    }
    __syncthreads();
  }
}

// ---------------- host ----------------
static void* sym(const void* s) { void* p = nullptr; cudaGetSymbolAddress(&p, s); return p; }

extern "C" void kernel_launch(void* const* d_in, const int* in_sizes, int n_in,
                              void* d_out, int out_size)
{
  const int*   context = (const int*)  d_in[0];
  const int*   query   = (const int*)  d_in[1];
  const float* E       = (const float*)d_in[2];
  const float* ctx_Wih = (const float*)d_in[3];
  const float* ctx_Whh = (const float*)d_in[4];
  const float* ctx_bih = (const float*)d_in[5];
  const float* ctx_bhh = (const float*)d_in[6];
  const float* q_Wih   = (const float*)d_in[7];
  const float* q_Whh   = (const float*)d_in[8];
  const float* q_bih   = (const float*)d_in[9];
  const float* q_bhh   = (const float*)d_in[10];
  const float* Wq      = (const float*)d_in[11];
  const float* Wp      = (const float*)d_in[12];
  const float* Wr      = (const float*)d_in[13];
  const float* wv      = (const float*)d_in[14];
  const float* gate_b  = (const float*)d_in[15];
  // d_in[16] = attn_bias (softmax-invariant, unused)
  const float* m_Wih   = (const float*)d_in[17];
  const float* m_Whh   = (const float*)d_in[18];
  const float* m_bih   = (const float*)d_in[19];
  const float* m_bhh   = (const float*)d_in[20];
  const float* mr_Wih  = (const float*)d_in[21];
  const float* mr_Whh  = (const float*)d_in[22];
  const float* mr_bih  = (const float*)d_in[23];
  const float* mr_bhh  = (const float*)d_in[24];
  const float* ptr_W1  = (const float*)d_in[25];
  const float* ptr_W2  = (const float*)d_in[26];
  const float* ptr_v   = (const float*)d_in[27];
  const float* d_Wih   = (const float*)d_in[28];
  const float* d_Whh   = (const float*)d_in[29];
  const float* d_bih   = (const float*)d_in[30];
  const float* d_bhh   = (const float*)d_in[31];
  float* out = (float*)d_out;

  float* gictx = (float*)sym(g_gictx);
  float* giq   = (float*)sym(g_giq);
  float* Hp    = (float*)sym(g_Hp);
  float* Hq    = (float*)sym(g_Hq);
  float* whq   = (float*)sym(g_whq);
  float* preWp = (float*)sym(g_preWp);
  float* gixf  = (float*)sym(g_gixf);
  float* gixb  = (float*)sym(g_gixb);
  float* qpf   = (float*)sym(g_qpf);
  float* qpb   = (float*)sym(g_qpb);
  float* Hr    = (float*)sym(g_Hr);
  float* enc   = (float*)sym(g_enc);
  __nv_bfloat16* packs = (__nv_bfloat16*)sym(g_packsb);
  __nv_bfloat16* P_ctx = packs + 0*PACKB_ELEMS;
  __nv_bfloat16* P_q   = packs + 1*PACKB_ELEMS;
  __nv_bfloat16* P_m   = packs + 2*PACKB_ELEMS;
  __nv_bfloat16* P_mr  = packs + 3*PACKB_ELEMS;

  int pk_grid = (PACKB_ELEMS + 255)/256;
  pack_bf16_kernel<<<pk_grid,256>>>(ctx_Whh, P_ctx);
  pack_bf16_kernel<<<pk_grid,256>>>(q_Whh,   P_q);
  pack_bf16_kernel<<<pk_grid,256>>>(m_Whh,   P_m);
  pack_bf16_kernel<<<pk_grid,256>>>(mr_Whh,  P_mr);

  gemm_kernel<true,true><<<dim3(8,100),256>>>(E, context, ctx_Wih, ctx_bih, gictx, Bc*Tc, H3c, Hc, 150, 150);
  gemm_kernel<true,true><<<dim3(8,8),  256>>>(E, query,   q_Wih,   q_bih,   giq,   Bc*Jc, H3c, Hc, 150, 150);

  gru_scan_kernel<<<64,512>>>(gictx, giq, (const uint4*)P_ctx, (const uint4*)P_q,
                              ctx_bhh, q_bhh, Hp, Hq);

  gemm_kernel<false,false><<<dim3(3,8),  256>>>(Hq, nullptr, Wq, nullptr, whq,   Bc*Jc, Hc,  Hc, Hc, Hc);
  gemm_kernel<false,false><<<dim3(3,100),256>>>(Hp, nullptr, Wp, gate_b,  preWp, Bc*Tc, Hc,  Hc, Hc, Hc);
  gemm_kernel<true, false><<<dim3(8,100),256>>>(Hp, nullptr, m_Wih,  m_bih,  gixf, Bc*Tc, H3c, Hc, Hc, 2*Hc);
  gemm_kernel<true, false><<<dim3(8,100),256>>>(Hp, nullptr, mr_Wih, mr_bih, gixb, Bc*Tc, H3c, Hc, Hc, 2*Hc);
  gemm_kernel<true, false><<<dim3(8,8),  256>>>(Hq, nullptr, m_Wih  + Hc, nullptr, qpf, Bc*Jc, H3c, Hc, Hc, 2*Hc);
  gemm_kernel<true, false><<<dim3(8,8),  256>>>(Hq, nullptr, mr_Wih + Hc, nullptr, qpb, Bc*Jc, H3c, Hc, Hc, 2*Hc);

  cudaFuncSetAttribute(match_kernel, cudaFuncAttributeMaxDynamicSharedMemorySize, DSMEM_BYTES);
  match_kernel<<<64, MATCH_THREADS, DSMEM_BYTES>>>(
      whq, preWp, gixf, gixb, qpf, qpb, Wr, wv,
      (const uint4*)P_m, (const uint4*)P_mr, m_bhh, mr_bhh, Hr);

  gemm_kernel<false,false><<<dim3(5,101),256>>>(Hr, nullptr, ptr_W1, nullptr, enc, Bc*TP1c, H2c, H2c, H2c, H2c);

  ptr_kernel<<<32,512>>>(Hr, enc, ptr_W2, ptr_v, d_Wih, d_Whh, d_bih, d_bhh, out);
}